// round 6
// baseline (speedup 1.0000x reference)
#include <cuda_runtime.h>
#include <cuda_bf16.h>
#include <math.h>
#include <stdint.h>

#define NB 2
#define NS 2048
#define NE 1024
#define NH 16
#define ND 64
#define NT 32            // NS / 64 key tiles
#define NEGV (-1e9f)
#define QSCALE 0.125f    // 1/sqrt(64)

// Scratch (allocation-free rule: __device__ globals)
__device__ float g_v[NB*NH*NS*ND];              // fp32 projected V (exact path)
__device__ float g_sufx[NB*NH*NS*ND];           // per-row exclusive suffix: sum_{k>s} v[k][d]
__device__ float g_vt[NB*NH*ND];                // total sum_k v[k][d]
__device__ __nv_bfloat16 g_qb[NB*NH*NS*ND];     // bf16 Q (pre-scaled by 1/8)
__device__ __nv_bfloat16 g_kb[NB*NH*NS*ND];     // bf16 K
__device__ __nv_bfloat16 g_vtb[NB*NH*NS*ND];    // bf16 V, transposed within each 64-tile: [bh][t][d][64]
// bf16 inputs: x: 0=query 1=key 2=value_hi 3=value_lo ; w: 0=Wq 1=Wk 2=Wv_hi 3=Wv_lo
__device__ __nv_bfloat16 g_xb[4u*4096*1024];
__device__ __nv_bfloat16 g_wb[4u*1024*1024];

// ---------------------------------------------------------------------------
__device__ __forceinline__ void mma16816(float* c, const uint32_t* a, const uint32_t* b) {
    asm volatile("mma.sync.aligned.m16n8k16.row.col.f32.bf16.bf16.f32 "
        "{%0,%1,%2,%3}, {%4,%5,%6,%7}, {%8,%9}, {%0,%1,%2,%3};"
        : "+f"(c[0]), "+f"(c[1]), "+f"(c[2]), "+f"(c[3])
        : "r"(a[0]), "r"(a[1]), "r"(a[2]), "r"(a[3]), "r"(b[0]), "r"(b[1]));
}

// ---------------------------------------------------------------------------
// Kernel 0: fp32 -> bf16 (hi), optionally also residual (lo) into next slice.
// ---------------------------------------------------------------------------
__global__ void f2bf_kernel(const float4* __restrict__ src, int which, int split, int n4)
{
    int i = blockIdx.x * blockDim.x + threadIdx.x;
    if (i >= n4) return;
    __nv_bfloat16* hi = (which < 4)
        ? g_xb + (size_t)which * 4096 * 1024
        : g_wb + (size_t)(which - 4) * 1024 * 1024;
    size_t loOff = (which < 4) ? (size_t)4096 * 1024 : (size_t)1024 * 1024;

    float4 v = src[i];
    __nv_bfloat16 h0 = __float2bfloat16(v.x), h1 = __float2bfloat16(v.y);
    __nv_bfloat16 h2 = __float2bfloat16(v.z), h3 = __float2bfloat16(v.w);
    __nv_bfloat162* dh = (__nv_bfloat162*)hi;
    dh[2*i]   = __nv_bfloat162(h0, h1);
    dh[2*i+1] = __nv_bfloat162(h2, h3);
    if (split) {
        __nv_bfloat162* dl = (__nv_bfloat162*)(hi + loOff);
        dl[2*i]   = __nv_bfloat162(__float2bfloat16(v.x - __bfloat162float(h0)),
                                   __float2bfloat16(v.y - __bfloat162float(h1)));
        dl[2*i+1] = __nv_bfloat162(__float2bfloat16(v.z - __bfloat162float(h2)),
                                   __float2bfloat16(v.w - __bfloat162float(h3)));
    }
}

// ---------------------------------------------------------------------------
// Kernel 1: projections via mma.sync bf16.
// z = 0: Q -> g_qb bf16 (scaled), 1: K -> g_kb bf16, 2: V (3-mma split) -> g_v fp32 + g_vtb bf16^T
// Block 256 thr = 8 warps as 4(m) x 2(n); warp tile 32x32; K-chunk 64.
// ---------------------------------------------------------------------------
#define PADW 72   // bf16 elements per smem row

__global__ __launch_bounds__(256) void proj_mma(
    const float* __restrict__ bq, const float* __restrict__ bk, const float* __restrict__ bv)
{
    extern __shared__ __align__(16) char smraw[];
    __nv_bfloat16* Xh = (__nv_bfloat16*)smraw;       // [128][PADW]
    __nv_bfloat16* Wh = Xh + 128 * PADW;             // [64][PADW]
    __nv_bfloat16* Xl = Wh + 64 * PADW;              // [128][PADW] (V only)
    __nv_bfloat16* Wl = Xl + 128 * PADW;             // [64][PADW]  (V only)

    const int z = blockIdx.z;
    const int split = (z == 2);
    const __nv_bfloat16* Xg  = g_xb + (size_t)z * 4096 * 1024;
    const __nv_bfloat16* Wg  = g_wb + (size_t)z * 1024 * 1024;
    const __nv_bfloat16* XgL = Xg + (size_t)4096 * 1024;
    const __nv_bfloat16* WgL = Wg + (size_t)1024 * 1024;
    const float* bias = (z == 0) ? bq : (z == 1) ? bk : bv;

    const int h  = blockIdx.x;
    const int m0 = blockIdx.y * 128;
    const int tid = threadIdx.x;
    const int wid = tid >> 5, lane = tid & 31;
    const int warpM = wid >> 1, warpN = wid & 1;
    const int gp = lane >> 2, tig = lane & 3;

    float acc[2][4][4] = {};

    for (int c = 0; c < 16; c++) {
        const int k0 = c * 64;
        __syncthreads();
        #pragma unroll
        for (int j = 0; j < 4; j++) {
            int u = tid + j * 256;
            int r = u >> 3, cg = (u & 7) * 8;
            *(uint4*)&Xh[r * PADW + cg] = *(const uint4*)(Xg + (size_t)(m0 + r) * NE + k0 + cg);
            if (split)
                *(uint4*)&Xl[r * PADW + cg] = *(const uint4*)(XgL + (size_t)(m0 + r) * NE + k0 + cg);
        }
        #pragma unroll
        for (int j = 0; j < 2; j++) {
            int u = tid + j * 256;
            int r = u >> 3, cg = (u & 7) * 8;
            *(uint4*)&Wh[r * PADW + cg] = *(const uint4*)(Wg + (size_t)(h * 64 + r) * NE + k0 + cg);
            if (split)
                *(uint4*)&Wl[r * PADW + cg] = *(const uint4*)(WgL + (size_t)(h * 64 + r) * NE + k0 + cg);
        }
        __syncthreads();

        #pragma unroll
        for (int ks = 0; ks < 4; ks++) {
            const int kc = ks * 16 + tig * 2;
            uint32_t a[2][4], b[4][2], al[2][4], bl[4][2];
            #pragma unroll
            for (int mi = 0; mi < 2; mi++) {
                const int r = warpM * 32 + mi * 16 + gp;
                a[mi][0] = *(const uint32_t*)&Xh[(r    ) * PADW + kc];
                a[mi][1] = *(const uint32_t*)&Xh[(r + 8) * PADW + kc];
                a[mi][2] = *(const uint32_t*)&Xh[(r    ) * PADW + kc + 8];
                a[mi][3] = *(const uint32_t*)&Xh[(r + 8) * PADW + kc + 8];
            }
            #pragma unroll
            for (int ni = 0; ni < 4; ni++) {
                const int n = warpN * 32 + ni * 8 + gp;
                b[ni][0] = *(const uint32_t*)&Wh[n * PADW + kc];
                b[ni][1] = *(const uint32_t*)&Wh[n * PADW + kc + 8];
            }
            if (split) {
                #pragma unroll
                for (int mi = 0; mi < 2; mi++) {
                    const int r = warpM * 32 + mi * 16 + gp;
                    al[mi][0] = *(const uint32_t*)&Xl[(r    ) * PADW + kc];
                    al[mi][1] = *(const uint32_t*)&Xl[(r + 8) * PADW + kc];
                    al[mi][2] = *(const uint32_t*)&Xl[(r    ) * PADW + kc + 8];
                    al[mi][3] = *(const uint32_t*)&Xl[(r + 8) * PADW + kc + 8];
                }
                #pragma unroll
                for (int ni = 0; ni < 4; ni++) {
                    const int n = warpN * 32 + ni * 8 + gp;
                    bl[ni][0] = *(const uint32_t*)&Wl[n * PADW + kc];
                    bl[ni][1] = *(const uint32_t*)&Wl[n * PADW + kc + 8];
                }
            }
            #pragma unroll
            for (int mi = 0; mi < 2; mi++)
                #pragma unroll
                for (int ni = 0; ni < 4; ni++) {
                    mma16816(acc[mi][ni], a[mi], b[ni]);
                    if (split) {
                        mma16816(acc[mi][ni], a[mi], bl[ni]);
                        mma16816(acc[mi][ni], al[mi], b[ni]);
                    }
                }
        }
    }

    const int b   = m0 >> 11;
    const int s0  = m0 & (NS - 1);
    const int bh  = b * NH + h;
    const float sc = (z == 0) ? QSCALE : 1.0f;
    #pragma unroll
    for (int mi = 0; mi < 2; mi++)
        #pragma unroll
        for (int ni = 0; ni < 4; ni++) {
            const int r  = warpM * 32 + mi * 16 + gp;
            const int cn = warpN * 32 + ni * 8 + tig * 2;
            const float bx = bias[h * 64 + cn], by = bias[h * 64 + cn + 1];
            #pragma unroll
            for (int half = 0; half < 2; half++) {
                const int rr = r + half * 8;
                const int s  = s0 + rr;
                float v0 = acc[mi][ni][2*half+0] + bx;
                float v1 = acc[mi][ni][2*half+1] + by;
                if (z < 2) {
                    __nv_bfloat16* dst = (z == 0) ? g_qb : g_kb;
                    __nv_bfloat162 p = __floats2bfloat162_rn(v0 * sc, v1 * sc);
                    *(__nv_bfloat162*)&dst[((size_t)bh * NS + s) * ND + cn] = p;
                } else {
                    *(float2*)&g_v[((size_t)bh * NS + s) * ND + cn] = make_float2(v0, v1);
                    // transposed bf16 within the 64-tile: [bh][t][d][j]
                    const int t = s >> 6, j = s & 63;
                    g_vtb[(((size_t)bh * NT + t) * ND + cn    ) * 64 + j] = __float2bfloat16(v0);
                    g_vtb[(((size_t)bh * NT + t) * ND + cn + 1) * 64 + j] = __float2bfloat16(v1);
                }
            }
        }
}

// ---------------------------------------------------------------------------
// Kernel 2: per-row exclusive suffix sums of V + total (fp32, exact).
// ---------------------------------------------------------------------------
__global__ void suffix_kernel()
{
    const int bh = blockIdx.x;
    const int d  = threadIdx.x;
    const float* v = g_v + (size_t)bh * NS * ND;
    float* sx = g_sufx + (size_t)bh * NS * ND;
    float acc = 0.f;
    for (int s = NS - 1; s >= 0; s--) {
        sx[(size_t)s * ND + d] = acc;      // exclusive: sum over k > s
        acc += v[(size_t)s * ND + d];
    }
    g_vt[bh * ND + d] = acc;
}

// ---------------------------------------------------------------------------
// Kernel 3: attention via mma.sync bf16.
// out[q,d] = sum_{unmasked k} s[q,k]*v[k,d] + NEG*sufx[q,d] - lse[q]*vt[d]
// ---------------------------------------------------------------------------
__global__ __launch_bounds__(256) void attn_mma(
    const float* __restrict__ pos_bias, float* __restrict__ out)
{
    extern __shared__ __align__(16) char smr[];
    __nv_bfloat16* Qb = (__nv_bfloat16*)smr;        // [64][72]
    __nv_bfloat16* Kb = Qb + 64 * PADW;             // [64][72]
    __nv_bfloat16* Vt = Kb + 64 * PADW;             // [64 d][72 k]
    __nv_bfloat16* Sb = Vt + 64 * PADW;             // [64 q][72 k]
    float* posw  = (float*)(Sb + 64 * PADW);        // [128]
    float* row_m = posw + 128;                      // [64]
    float* row_l = row_m + 64;                      // [64]
    float* lse_s = row_l + 64;                      // [64]

    const int tq = blockIdx.x;
    const int h  = blockIdx.y;
    const int b  = blockIdx.z;
    const int bh = b * NH + h;
    const int q0 = tq * 64;
    const int tid = threadIdx.x;
    const int wid = tid >> 5, lane = tid & 31;
    const int warpM = wid >> 1, warpN = wid & 1;
    const int gp = lane >> 2, tig = lane & 3;
    const int rbase = warpM * 16 + gp;

    // load Q tile (already scaled) once
    #pragma unroll
    for (int j = 0; j < 2; j++) {
        int u = tid + j * 256;
        int r = u >> 3, cg = (u & 7) * 8;
        *(uint4*)&Qb[r * PADW + cg] = *(const uint4*)(g_qb + ((size_t)bh * NS + q0 + r) * ND + cg);
    }
    if (tid < 64) { row_m[tid] = -1e30f; row_l[tid] = 0.f; }

    float oacc[4][4] = {};

    for (int t = 0; t <= tq; t++) {
        const int k0 = t * 64;
        const int diag = (t == tq);
        __syncthreads();
        #pragma unroll
        for (int j = 0; j < 2; j++) {
            int u = tid + j * 256;
            int r = u >> 3, cg = (u & 7) * 8;
            *(uint4*)&Kb[r * PADW + cg] = *(const uint4*)(g_kb + ((size_t)bh * NS + k0 + r) * ND + cg);
            *(uint4*)&Vt[r * PADW + cg] = *(const uint4*)(g_vtb + (((size_t)bh * NT + t) * ND + r) * 64 + cg);
        }
        if (tid < 128) {
            int idx = q0 - k0 - 63 + tid + NS - 1;   // into pos row [0, 2S-2]
            posw[tid] = (idx <= 2 * NS - 2) ? pos_bias[(size_t)h * (2 * NS - 1) + idx] : 0.f;
        }
        __syncthreads();

        // ---- S = Q.K^T (fp32 accum) ----
        float cS[4][4] = {};
        #pragma unroll
        for (int ks = 0; ks < 4; ks++) {
            const int kc = ks * 16 + tig * 2;
            uint32_t a[4], bb[4][2];
            a[0] = *(const uint32_t*)&Qb[(rbase    ) * PADW + kc];
            a[1] = *(const uint32_t*)&Qb[(rbase + 8) * PADW + kc];
            a[2] = *(const uint32_t*)&Qb[(rbase    ) * PADW + kc + 8];
            a[3] = *(const uint32_t*)&Qb[(rbase + 8) * PADW + kc + 8];
            #pragma unroll
            for (int ni = 0; ni < 4; ni++) {
                const int n = warpN * 32 + ni * 8 + gp;
                bb[ni][0] = *(const uint32_t*)&Kb[n * PADW + kc];
                bb[ni][1] = *(const uint32_t*)&Kb[n * PADW + kc + 8];
            }
            #pragma unroll
            for (int ni = 0; ni < 4; ni++) mma16816(cS[ni], a, bb[ni]);
        }

        // ---- bias + mask -> Sb bf16 (masked entries stored as 0) ----
        #pragma unroll
        for (int ni = 0; ni < 4; ni++) {
            const int kcol = warpN * 32 + ni * 8 + tig * 2;
            #pragma unroll
            for (int half = 0; half < 2; half++) {
                const int r = rbase + half * 8;
                float v0 = cS[ni][2*half+0] + posw[r - kcol + 63];
                float v1 = cS[ni][2*half+1] + posw[r - kcol + 62];
                if (diag) {
                    if (kcol     > r) v0 = 0.f;
                    if (kcol + 1 > r) v1 = 0.f;
                }
                *(__nv_bfloat162*)&Sb[r * PADW + kcol] = __floats2bfloat162_rn(v0, v1);
            }
        }
        __syncthreads();

        // ---- online lse: 4 threads per row ----
        {
            const int rowi = tid >> 2, seg = tid & 3;
            const int jmax = diag ? rowi : 63;
            float m_loc = -1e30f;
            #pragma unroll 4
            for (int j = seg * 16; j < seg * 16 + 16; j++)
                if (j <= jmax) m_loc = fmaxf(m_loc, __bfloat162float(Sb[rowi * PADW + j]));
            float l_loc = 0.f;
            #pragma unroll 4
            for (int j = seg * 16; j < seg * 16 + 16; j++)
                if (j <= jmax) l_loc += __expf(__bfloat162float(Sb[rowi * PADW + j]) - m_loc);
            #pragma unroll
            for (int d = 1; d < 4; d <<= 1) {
                float mo = __shfl_xor_sync(0xffffffffu, m_loc, d);
                float lo = __shfl_xor_sync(0xffffffffu, l_loc, d);
                float mn = fmaxf(m_loc, mo);
                l_loc = l_loc * __expf(m_loc - mn) + lo * __expf(mo - mn);
                m_loc = mn;
            }
            if (seg == 0) {
                float mo = row_m[rowi], lo = row_l[rowi];
                float mn = fmaxf(mo, m_loc);
                row_l[rowi] = lo * __expf(mo - mn) + l_loc * __expf(m_loc - mn);
                row_m[rowi] = mn;
            }
        }

        // ---- O += S.V ----
        #pragma unroll
        for (int ks = 0; ks < 4; ks++) {
            const int kc = ks * 16 + tig * 2;
            uint32_t a[4], bb[4][2];
            a[0] = *(const uint32_t*)&Sb[(rbase    ) * PADW + kc];
            a[1] = *(const uint32_t*)&Sb[(rbase + 8) * PADW + kc];
            a[2] = *(const uint32_t*)&Sb[(rbase    ) * PADW + kc + 8];
            a[3] = *(const uint32_t*)&Sb[(rbase + 8) * PADW + kc + 8];
            #pragma unroll
            for (int ni = 0; ni < 4; ni++) {
                const int n = warpN * 32 + ni * 8 + gp;   // d index
                bb[ni][0] = *(const uint32_t*)&Vt[n * PADW + kc];
                bb[ni][1] = *(const uint32_t*)&Vt[n * PADW + kc + 8];
            }
            #pragma unroll
            for (int ni = 0; ni < 4; ni++) mma16816(oacc[ni], a, bb[ni]);
        }
    }

    __syncthreads();
    if (tid < 64) lse_s[tid] = row_m[tid] + logf(row_l[tid]);
    __syncthreads();

    const float lse0 = lse_s[rbase], lse1 = lse_s[rbase + 8];
    #pragma unroll
    for (int ni = 0; ni < 4; ni++) {
        const int d = warpN * 32 + ni * 8 + tig * 2;
        float2 vt2 = *(const float2*)&g_vt[bh * ND + d];
        const int q0r = q0 + rbase;
        float2 sx0 = *(const float2*)&g_sufx[((size_t)bh * NS + q0r    ) * ND + d];
        float2 sx1 = *(const float2*)&g_sufx[((size_t)bh * NS + q0r + 8) * ND + d];
        float2 o0, o1;
        o0.x = oacc[ni][0] + NEGV * sx0.x - lse0 * vt2.x;
        o0.y = oacc[ni][1] + NEGV * sx0.y - lse0 * vt2.y;
        o1.x = oacc[ni][2] + NEGV * sx1.x - lse1 * vt2.x;
        o1.y = oacc[ni][3] + NEGV * sx1.y - lse1 * vt2.y;
        *(float2*)&out[(((size_t)b * NS + q0r    ) * NH + h) * ND + d] = o0;
        *(float2*)&out[(((size_t)b * NS + q0r + 8) * NH + h) * ND + d] = o1;
    }
}

// ---------------------------------------------------------------------------
extern "C" void kernel_launch(void* const* d_in, const int* in_sizes, int n_in,
                              void* d_out, int out_size)
{
    (void)in_sizes; (void)n_in; (void)out_size;
    const float* query = (const float*)d_in[0];
    const float* key_  = (const float*)d_in[1];
    const float* value = (const float*)d_in[2];
    const float* bq    = (const float*)d_in[4];
    const float* bk    = (const float*)d_in[6];
    const float* bv    = (const float*)d_in[8];
    const float* Wq    = (const float*)d_in[3];
    const float* Wk    = (const float*)d_in[5];
    const float* Wv    = (const float*)d_in[7];
    const float* pos   = (const float*)d_in[9];

    const int n4x = 4096 * 1024 / 4, n4w = 1024 * 1024 / 4;
    f2bf_kernel<<<n4x / 256, 256>>>((const float4*)query, 0, 0, n4x);
    f2bf_kernel<<<n4x / 256, 256>>>((const float4*)key_,  1, 0, n4x);
    f2bf_kernel<<<n4x / 256, 256>>>((const float4*)value, 2, 1, n4x);
    f2bf_kernel<<<n4w / 256, 256>>>((const float4*)Wq,    4, 0, n4w);
    f2bf_kernel<<<n4w / 256, 256>>>((const float4*)Wk,    5, 0, n4w);
    f2bf_kernel<<<n4w / 256, 256>>>((const float4*)Wv,    6, 1, n4w);

    const int PROJ_SMEM = (128 * PADW + 64 * PADW) * 2 * 2;   // 55296 B
    cudaFuncSetAttribute(proj_mma, cudaFuncAttributeMaxDynamicSharedMemorySize, PROJ_SMEM);
    proj_mma<<<dim3(16, 32, 3), 256, PROJ_SMEM>>>(bq, bk, bv);

    suffix_kernel<<<dim3(NB * NH), 64>>>();

    const int ATTN_SMEM = 4 * 64 * PADW * 2 + (128 + 192) * 4;  // 38144 B
    attn_mma<<<dim3(NT, NH, NB), 256, ATTN_SMEM>>>(pos, (float*)d_out);
}

// round 7
// speedup vs baseline: 2.5371x; 2.5371x over previous
#include <cuda_runtime.h>
#include <cuda_bf16.h>
#include <math.h>
#include <stdint.h>

#define NB 2
#define NS 2048
#define NE 1024
#define NH 16
#define ND 64
#define NT 32            // NS / 64 key tiles
#define NEGV (-1e9f)
#define NEGM (-1e30f)
#define QSCALE 0.125f    // 1/sqrt(64)
#define PADW 72          // bf16 elements per smem row

// Scratch (allocation-free rule: __device__ globals)
__device__ float g_v[NB*NH*NS*ND];              // fp32 projected V (exact path)
__device__ float g_sufx[NB*NH*NS*ND];           // per-row exclusive suffix: sum_{k>s} v[k][d]
__device__ float g_vt[NB*NH*ND];                // total sum_k v[k][d]
__device__ float g_tsum[NB*NH*NT*ND];           // per-tile V sums
__device__ float g_tsuf[NB*NH*NT*ND];           // exclusive tile-level suffix
__device__ __nv_bfloat16 g_qb[NB*NH*NS*ND];     // bf16 Q (pre-scaled by 1/8)
__device__ __nv_bfloat16 g_kb[NB*NH*NS*ND];     // bf16 K
__device__ __nv_bfloat16 g_vtb[NB*NH*NS*ND];    // bf16 V transposed per 64-tile: [bh][t][d][64]
// bf16 inputs: x: 0=query 1=key 2=value_hi 3=value_lo ; w: 0=Wq 1=Wk 2=Wv_hi 3=Wv_lo
__device__ __nv_bfloat16 g_xb[4u*4096*1024];
__device__ __nv_bfloat16 g_wb[4u*1024*1024];

// ---------------------------------------------------------------------------
__device__ __forceinline__ void mma16816(float* c, const uint32_t* a, const uint32_t* b) {
    asm volatile("mma.sync.aligned.m16n8k16.row.col.f32.bf16.bf16.f32 "
        "{%0,%1,%2,%3}, {%4,%5,%6,%7}, {%8,%9}, {%0,%1,%2,%3};"
        : "+f"(c[0]), "+f"(c[1]), "+f"(c[2]), "+f"(c[3])
        : "r"(a[0]), "r"(a[1]), "r"(a[2]), "r"(a[3]), "r"(b[0]), "r"(b[1]));
}
__device__ __forceinline__ uint32_t pack_bf16x2(float a, float b) {
    __nv_bfloat162 t = __floats2bfloat162_rn(a, b);
    return *(uint32_t*)&t;
}

// ---------------------------------------------------------------------------
// Kernel 0: fp32 -> bf16 (hi), optionally also residual (lo) into next slice.
// ---------------------------------------------------------------------------
__global__ void f2bf_kernel(const float4* __restrict__ src, int which, int split, int n4)
{
    int i = blockIdx.x * blockDim.x + threadIdx.x;
    if (i >= n4) return;
    __nv_bfloat16* hi = (which < 4)
        ? g_xb + (size_t)which * 4096 * 1024
        : g_wb + (size_t)(which - 4) * 1024 * 1024;
    size_t loOff = (which < 4) ? (size_t)4096 * 1024 : (size_t)1024 * 1024;

    float4 v = src[i];
    __nv_bfloat16 h0 = __float2bfloat16(v.x), h1 = __float2bfloat16(v.y);
    __nv_bfloat16 h2 = __float2bfloat16(v.z), h3 = __float2bfloat16(v.w);
    __nv_bfloat162* dh = (__nv_bfloat162*)hi;
    dh[2*i]   = __nv_bfloat162(h0, h1);
    dh[2*i+1] = __nv_bfloat162(h2, h3);
    if (split) {
        __nv_bfloat162* dl = (__nv_bfloat162*)(hi + loOff);
        dl[2*i]   = __nv_bfloat162(__float2bfloat16(v.x - __bfloat162float(h0)),
                                   __float2bfloat16(v.y - __bfloat162float(h1)));
        dl[2*i+1] = __nv_bfloat162(__float2bfloat16(v.z - __bfloat162float(h2)),
                                   __float2bfloat16(v.w - __bfloat162float(h3)));
    }
}

// ---------------------------------------------------------------------------
// Kernel 1: projections via mma.sync bf16.
// z = 0: Q -> g_qb bf16 (scaled), 1: K -> g_kb, 2: V (3-mma split) -> g_v fp32 + g_vtb bf16^T
// ---------------------------------------------------------------------------
__global__ __launch_bounds__(256) void proj_mma(
    const float* __restrict__ bq, const float* __restrict__ bk, const float* __restrict__ bv)
{
    extern __shared__ __align__(16) char smraw[];
    __nv_bfloat16* Xh = (__nv_bfloat16*)smraw;       // [128][PADW]
    __nv_bfloat16* Wh = Xh + 128 * PADW;             // [64][PADW]
    __nv_bfloat16* Xl = Wh + 64 * PADW;              // [128][PADW] (V only)
    __nv_bfloat16* Wl = Xl + 128 * PADW;             // [64][PADW]  (V only)

    const int z = blockIdx.z;
    const int split = (z == 2);
    const __nv_bfloat16* Xg  = g_xb + (size_t)z * 4096 * 1024;
    const __nv_bfloat16* Wg  = g_wb + (size_t)z * 1024 * 1024;
    const __nv_bfloat16* XgL = Xg + (size_t)4096 * 1024;
    const __nv_bfloat16* WgL = Wg + (size_t)1024 * 1024;
    const float* bias = (z == 0) ? bq : (z == 1) ? bk : bv;

    const int h  = blockIdx.x;
    const int m0 = blockIdx.y * 128;
    const int tid = threadIdx.x;
    const int wid = tid >> 5, lane = tid & 31;
    const int warpM = wid >> 1, warpN = wid & 1;
    const int gp = lane >> 2, tig = lane & 3;

    float acc[2][4][4] = {};

    for (int c = 0; c < 16; c++) {
        const int k0 = c * 64;
        __syncthreads();
        #pragma unroll
        for (int j = 0; j < 4; j++) {
            int u = tid + j * 256;
            int r = u >> 3, cg = (u & 7) * 8;
            *(uint4*)&Xh[r * PADW + cg] = *(const uint4*)(Xg + (size_t)(m0 + r) * NE + k0 + cg);
            if (split)
                *(uint4*)&Xl[r * PADW + cg] = *(const uint4*)(XgL + (size_t)(m0 + r) * NE + k0 + cg);
        }
        #pragma unroll
        for (int j = 0; j < 2; j++) {
            int u = tid + j * 256;
            int r = u >> 3, cg = (u & 7) * 8;
            *(uint4*)&Wh[r * PADW + cg] = *(const uint4*)(Wg + (size_t)(h * 64 + r) * NE + k0 + cg);
            if (split)
                *(uint4*)&Wl[r * PADW + cg] = *(const uint4*)(WgL + (size_t)(h * 64 + r) * NE + k0 + cg);
        }
        __syncthreads();

        #pragma unroll
        for (int ks = 0; ks < 4; ks++) {
            const int kc = ks * 16 + tig * 2;
            uint32_t a[2][4], b[4][2], al[2][4], bl[4][2];
            #pragma unroll
            for (int mi = 0; mi < 2; mi++) {
                const int r = warpM * 32 + mi * 16 + gp;
                a[mi][0] = *(const uint32_t*)&Xh[(r    ) * PADW + kc];
                a[mi][1] = *(const uint32_t*)&Xh[(r + 8) * PADW + kc];
                a[mi][2] = *(const uint32_t*)&Xh[(r    ) * PADW + kc + 8];
                a[mi][3] = *(const uint32_t*)&Xh[(r + 8) * PADW + kc + 8];
            }
            #pragma unroll
            for (int ni = 0; ni < 4; ni++) {
                const int n = warpN * 32 + ni * 8 + gp;
                b[ni][0] = *(const uint32_t*)&Wh[n * PADW + kc];
                b[ni][1] = *(const uint32_t*)&Wh[n * PADW + kc + 8];
            }
            if (split) {
                #pragma unroll
                for (int mi = 0; mi < 2; mi++) {
                    const int r = warpM * 32 + mi * 16 + gp;
                    al[mi][0] = *(const uint32_t*)&Xl[(r    ) * PADW + kc];
                    al[mi][1] = *(const uint32_t*)&Xl[(r + 8) * PADW + kc];
                    al[mi][2] = *(const uint32_t*)&Xl[(r    ) * PADW + kc + 8];
                    al[mi][3] = *(const uint32_t*)&Xl[(r + 8) * PADW + kc + 8];
                }
                #pragma unroll
                for (int ni = 0; ni < 4; ni++) {
                    const int n = warpN * 32 + ni * 8 + gp;
                    bl[ni][0] = *(const uint32_t*)&Wl[n * PADW + kc];
                    bl[ni][1] = *(const uint32_t*)&Wl[n * PADW + kc + 8];
                }
            }
            #pragma unroll
            for (int mi = 0; mi < 2; mi++)
                #pragma unroll
                for (int ni = 0; ni < 4; ni++) {
                    mma16816(acc[mi][ni], a[mi], b[ni]);
                    if (split) {
                        mma16816(acc[mi][ni], a[mi], bl[ni]);
                        mma16816(acc[mi][ni], al[mi], b[ni]);
                    }
                }
        }
    }

    const int b   = m0 >> 11;
    const int s0  = m0 & (NS - 1);
    const int bh  = b * NH + h;
    __syncthreads();   // everyone done reading Xh/Wh before smem reuse

    if (z < 2) {
        const float sc = (z == 0) ? QSCALE : 1.0f;
        __nv_bfloat16* dst = (z == 0) ? g_qb : g_kb;
        #pragma unroll
        for (int mi = 0; mi < 2; mi++)
            #pragma unroll
            for (int ni = 0; ni < 4; ni++) {
                const int r  = warpM * 32 + mi * 16 + gp;
                const int cn = warpN * 32 + ni * 8 + tig * 2;
                const float bx = bias[h * 64 + cn], by = bias[h * 64 + cn + 1];
                #pragma unroll
                for (int half = 0; half < 2; half++) {
                    const int s = s0 + r + half * 8;
                    float v0 = (acc[mi][ni][2*half+0] + bx) * sc;
                    float v1 = (acc[mi][ni][2*half+1] + by) * sc;
                    *(uint32_t*)&dst[((size_t)bh * NS + s) * ND + cn] = pack_bf16x2(v0, v1);
                }
            }
    } else {
        float* Vst = (float*)smraw;   // [128][67] staging (67: conflict-free transpose)
        #pragma unroll
        for (int mi = 0; mi < 2; mi++)
            #pragma unroll
            for (int ni = 0; ni < 4; ni++) {
                const int r  = warpM * 32 + mi * 16 + gp;
                const int cn = warpN * 32 + ni * 8 + tig * 2;
                const float bx = bias[h * 64 + cn], by = bias[h * 64 + cn + 1];
                #pragma unroll
                for (int half = 0; half < 2; half++) {
                    const int rr = r + half * 8;
                    Vst[rr * 67 + cn    ] = acc[mi][ni][2*half+0] + bx;
                    Vst[rr * 67 + cn + 1] = acc[mi][ni][2*half+1] + by;
                }
            }
        __syncthreads();
        // coalesced fp32 V
        #pragma unroll
        for (int i = 0; i < 8; i++) {
            int u = tid + i * 256;
            int r = u >> 4, c4 = (u & 15) * 4;
            float4 w = make_float4(Vst[r*67+c4], Vst[r*67+c4+1], Vst[r*67+c4+2], Vst[r*67+c4+3]);
            *(float4*)&g_v[((size_t)bh * NS + s0 + r) * ND + c4] = w;
        }
        // coalesced transposed bf16 V
        const int t0 = s0 >> 6;
        #pragma unroll
        for (int i = 0; i < 16; i++) {
            int u = tid + i * 256;
            int j = (u & 31) * 2, d = (u >> 5) & 63, tl = u >> 11;
            uint32_t p = pack_bf16x2(Vst[(tl*64 + j)*67 + d], Vst[(tl*64 + j + 1)*67 + d]);
            *(uint32_t*)&g_vtb[(((size_t)bh * NT + t0 + tl) * ND + d) * 64 + j] = p;
        }
    }
}

// ---------------------------------------------------------------------------
// Kernels 2a/2b/2c: parallel per-row exclusive suffix sums of V.
// ---------------------------------------------------------------------------
__global__ void tile_sum_kernel()
{
    const int bh = blockIdx.x, t = blockIdx.y, d = threadIdx.x;
    const float* v = g_v + ((size_t)bh * NS + t * 64) * ND + d;
    float a = 0.f;
    #pragma unroll 8
    for (int j = 0; j < 64; j++) a += v[(size_t)j * ND];
    g_tsum[((size_t)bh * NT + t) * ND + d] = a;
}
__global__ void tile_suffix_kernel()
{
    const int bh = blockIdx.x, d = threadIdx.x;
    float acc = 0.f;
    for (int t = NT - 1; t >= 0; t--) {
        float tv = g_tsum[((size_t)bh * NT + t) * ND + d];
        g_tsuf[((size_t)bh * NT + t) * ND + d] = acc;
        acc += tv;
    }
    g_vt[bh * ND + d] = acc;
}
__global__ void row_suffix_kernel()
{
    const int bh = blockIdx.x, t = blockIdx.y, d = threadIdx.x;
    float acc = g_tsuf[((size_t)bh * NT + t) * ND + d];
    const float* v = g_v + ((size_t)bh * NS + t * 64) * ND + d;
    float* sx = g_sufx + ((size_t)bh * NS + t * 64) * ND + d;
    for (int j = 63; j >= 0; j--) {
        sx[(size_t)j * ND] = acc;
        acc += v[(size_t)j * ND];
    }
}

// ---------------------------------------------------------------------------
// Kernel 3: register-resident flash-style attention (mma.sync bf16).
// k split across warpN; S frags repacked in-register as SV A-operands.
// ---------------------------------------------------------------------------
__global__ __launch_bounds__(256, 2) void attn_mma(
    const float* __restrict__ pos_bias, float* __restrict__ out)
{
    extern __shared__ __align__(16) char smr[];
    __nv_bfloat16* Qb = (__nv_bfloat16*)smr;        // [64][72]
    __nv_bfloat16* Kb = Qb + 64 * PADW;             // [64][72]
    __nv_bfloat16* Vt = Kb + 64 * PADW;             // [64 d][72 k]
    float* posw  = (float*)(Vt + 64 * PADW);        // [128]
    float* pm    = posw + 128;                      // [64][2]
    float* pl    = pm + 128;                        // [64][2]
    float* lse_s = pl + 128;                        // [64]
    float* Obuf  = (float*)smr;                     // overlay [64][66] (Qb/Kb region)

    const int tq = NT - 1 - blockIdx.x;             // heavy blocks first
    const int h  = blockIdx.y;
    const int b  = blockIdx.z;
    const int bh = b * NH + h;
    const int q0 = tq * 64;
    const int tid = threadIdx.x;
    const int wid = tid >> 5, lane = tid & 31;
    const int warpM = wid >> 1, warpN = wid & 1;
    const int gp = lane >> 2, tig = lane & 3;
    const int rbase = warpM * 16 + gp;

    #pragma unroll
    for (int j = 0; j < 2; j++) {
        int u = tid + j * 256;
        int r = u >> 3, cg = (u & 7) * 8;
        *(uint4*)&Qb[r * PADW + cg] = *(const uint4*)(g_qb + ((size_t)bh * NS + q0 + r) * ND + cg);
    }
    __syncthreads();
    uint32_t aq[4][4];                               // Q fragments, resident all tiles
    #pragma unroll
    for (int ks = 0; ks < 4; ks++) {
        const int kc = ks * 16 + tig * 2;
        aq[ks][0] = *(const uint32_t*)&Qb[(rbase    ) * PADW + kc];
        aq[ks][1] = *(const uint32_t*)&Qb[(rbase + 8) * PADW + kc];
        aq[ks][2] = *(const uint32_t*)&Qb[(rbase    ) * PADW + kc + 8];
        aq[ks][3] = *(const uint32_t*)&Qb[(rbase + 8) * PADW + kc + 8];
    }

    float oacc[8][4] = {};
    float m0r = NEGM, l0r = 0.f, m1r = NEGM, l1r = 0.f;

    for (int t = 0; t <= tq; t++) {
        const int k0 = t * 64;
        const bool diag = (t == tq);
        __syncthreads();
        #pragma unroll
        for (int j = 0; j < 2; j++) {
            int u = tid + j * 256;
            int r = u >> 3, cg = (u & 7) * 8;
            *(uint4*)&Kb[r * PADW + cg] = *(const uint4*)(g_kb + ((size_t)bh * NS + k0 + r) * ND + cg);
            *(uint4*)&Vt[r * PADW + cg] = *(const uint4*)(g_vtb + (((size_t)bh * NT + t) * ND + r) * 64 + cg);
        }
        if (tid < 128) {
            int idx = q0 - k0 - 63 + tid + NS - 1;
            posw[tid] = (idx <= 2 * NS - 2) ? pos_bias[(size_t)h * (2 * NS - 1) + idx] : 0.f;
        }
        __syncthreads();

        // ---- S = Q.K^T over this warp's k-half ----
        float cS[4][4] = {};
        #pragma unroll
        for (int ks = 0; ks < 4; ks++) {
            const int kc = ks * 16 + tig * 2;
            uint32_t bb[4][2];
            #pragma unroll
            for (int ni = 0; ni < 4; ni++) {
                const int n = warpN * 32 + ni * 8 + gp;
                bb[ni][0] = *(const uint32_t*)&Kb[n * PADW + kc];
                bb[ni][1] = *(const uint32_t*)&Kb[n * PADW + kc + 8];
            }
            #pragma unroll
            for (int ni = 0; ni < 4; ni++) mma16816(cS[ni], aq[ks], bb[ni]);
        }

        // ---- bias + mask in registers; pack SV A-frags; collect lse values ----
        float e0[8], e1[8];
        uint32_t sf[2][4];
        #pragma unroll
        for (int ni = 0; ni < 4; ni++) {
            const int kcol = warpN * 32 + ni * 8 + tig * 2;
            float v00 = cS[ni][0] + posw[rbase     - kcol + 63];
            float v01 = cS[ni][1] + posw[rbase     - kcol + 62];
            float v10 = cS[ni][2] + posw[rbase + 8 - kcol + 63];
            float v11 = cS[ni][3] + posw[rbase + 8 - kcol + 62];
            float p00 = v00, p01 = v01, p10 = v10, p11 = v11;
            if (diag) {
                if (kcol     > rbase)     { v00 = NEGM; p00 = 0.f; }
                if (kcol + 1 > rbase)     { v01 = NEGM; p01 = 0.f; }
                if (kcol     > rbase + 8) { v10 = NEGM; p10 = 0.f; }
                if (kcol + 1 > rbase + 8) { v11 = NEGM; p11 = 0.f; }
            }
            e0[ni*2] = v00; e0[ni*2+1] = v01;
            e1[ni*2] = v10; e1[ni*2+1] = v11;
            const int ks2 = ni >> 1;
            if ((ni & 1) == 0) {
                sf[ks2][0] = pack_bf16x2(p00, p01);
                sf[ks2][1] = pack_bf16x2(p10, p11);
            } else {
                sf[ks2][2] = pack_bf16x2(p00, p01);
                sf[ks2][3] = pack_bf16x2(p10, p11);
            }
        }
        // ---- online lse (register-only; garbage-partials killed by final combine) ----
        {
            float vm = e0[0];
            #pragma unroll
            for (int j = 1; j < 8; j++) vm = fmaxf(vm, e0[j]);
            float mn = fmaxf(m0r, vm);
            float s = 0.f;
            #pragma unroll
            for (int j = 0; j < 8; j++) s += __expf(e0[j] - mn);
            l0r = l0r * __expf(m0r - mn) + s; m0r = mn;
        }
        {
            float vm = e1[0];
            #pragma unroll
            for (int j = 1; j < 8; j++) vm = fmaxf(vm, e1[j]);
            float mn = fmaxf(m1r, vm);
            float s = 0.f;
            #pragma unroll
            for (int j = 0; j < 8; j++) s += __expf(e1[j] - mn);
            l1r = l1r * __expf(m1r - mn) + s; m1r = mn;
        }

        // ---- O += S.V over this warp's k-half (full 64 d) ----
        #pragma unroll
        for (int ks2 = 0; ks2 < 2; ks2++) {
            const int kc = warpN * 32 + ks2 * 16 + tig * 2;
            #pragma unroll
            for (int ni = 0; ni < 8; ni++) {
                const int n = ni * 8 + gp;
                uint32_t bb[2];
                bb[0] = *(const uint32_t*)&Vt[n * PADW + kc];
                bb[1] = *(const uint32_t*)&Vt[n * PADW + kc + 8];
                mma16816(oacc[ni], sf[ks2], bb);
            }
        }
    }

    __syncthreads();
    // reduce (m,l) across tig lanes
    #pragma unroll
    for (int d = 1; d < 4; d <<= 1) {
        float mo = __shfl_xor_sync(0xffffffffu, m0r, d);
        float lo = __shfl_xor_sync(0xffffffffu, l0r, d);
        float mn = fmaxf(m0r, mo);
        l0r = l0r * __expf(m0r - mn) + lo * __expf(mo - mn); m0r = mn;
        mo = __shfl_xor_sync(0xffffffffu, m1r, d);
        lo = __shfl_xor_sync(0xffffffffu, l1r, d);
        mn = fmaxf(m1r, mo);
        l1r = l1r * __expf(m1r - mn) + lo * __expf(mo - mn); m1r = mn;
    }
    if (tig == 0) {
        pm[rbase * 2 + warpN] = m0r;       pl[rbase * 2 + warpN] = l0r;
        pm[(rbase + 8) * 2 + warpN] = m1r; pl[(rbase + 8) * 2 + warpN] = l1r;
    }
    __syncthreads();
    if (tid < 64) {
        float ma = pm[tid*2], mb_ = pm[tid*2+1], la = pl[tid*2], lb = pl[tid*2+1];
        float mn = fmaxf(ma, mb_);
        lse_s[tid] = mn + logf(la * __expf(ma - mn) + lb * __expf(mb_ - mn));
    }
    __syncthreads();
    // cross-warpN O combine
    if (warpN == 1) {
        #pragma unroll
        for (int ni = 0; ni < 8; ni++) {
            const int d = ni * 8 + tig * 2;
            Obuf[rbase * 66 + d]           = oacc[ni][0];
            Obuf[rbase * 66 + d + 1]       = oacc[ni][1];
            Obuf[(rbase + 8) * 66 + d]     = oacc[ni][2];
            Obuf[(rbase + 8) * 66 + d + 1] = oacc[ni][3];
        }
    }
    __syncthreads();
    if (warpN == 0) {
        const float lse0 = lse_s[rbase], lse1 = lse_s[rbase + 8];
        const int q0r = q0 + rbase;
        #pragma unroll
        for (int ni = 0; ni < 8; ni++) {
            const int d = ni * 8 + tig * 2;
            float2 vt2 = *(const float2*)&g_vt[bh * ND + d];
            float2 sx0 = *(const float2*)&g_sufx[((size_t)bh * NS + q0r    ) * ND + d];
            float2 sx1 = *(const float2*)&g_sufx[((size_t)bh * NS + q0r + 8) * ND + d];
            float2 o0, o1;
            o0.x = oacc[ni][0] + Obuf[rbase * 66 + d]     + NEGV * sx0.x - lse0 * vt2.x;
            o0.y = oacc[ni][1] + Obuf[rbase * 66 + d + 1] + NEGV * sx0.y - lse0 * vt2.y;
            o1.x = oacc[ni][2] + Obuf[(rbase+8) * 66 + d]     + NEGV * sx1.x - lse1 * vt2.x;
            o1.y = oacc[ni][3] + Obuf[(rbase+8) * 66 + d + 1] + NEGV * sx1.y - lse1 * vt2.y;
            *(float2*)&out[(((size_t)b * NS + q0r    ) * NH + h) * ND + d] = o0;
            *(float2*)&out[(((size_t)b * NS + q0r + 8) * NH + h) * ND + d] = o1;
        }
    }
}

// ---------------------------------------------------------------------------
extern "C" void kernel_launch(void* const* d_in, const int* in_sizes, int n_in,
                              void* d_out, int out_size)
{
    (void)in_sizes; (void)n_in; (void)out_size;
    const float* query = (const float*)d_in[0];
    const float* key_  = (const float*)d_in[1];
    const float* value = (const float*)d_in[2];
    const float* Wq    = (const float*)d_in[3];
    const float* bq    = (const float*)d_in[4];
    const float* Wk    = (const float*)d_in[5];
    const float* bk    = (const float*)d_in[6];
    const float* Wv    = (const float*)d_in[7];
    const float* bv    = (const float*)d_in[8];
    const float* pos   = (const float*)d_in[9];

    const int n4x = 4096 * 1024 / 4, n4w = 1024 * 1024 / 4;
    f2bf_kernel<<<n4x / 256, 256>>>((const float4*)query, 0, 0, n4x);
    f2bf_kernel<<<n4x / 256, 256>>>((const float4*)key_,  1, 0, n4x);
    f2bf_kernel<<<n4x / 256, 256>>>((const float4*)value, 2, 1, n4x);
    f2bf_kernel<<<n4w / 256, 256>>>((const float4*)Wq,    4, 0, n4w);
    f2bf_kernel<<<n4w / 256, 256>>>((const float4*)Wk,    5, 0, n4w);
    f2bf_kernel<<<n4w / 256, 256>>>((const float4*)Wv,    6, 1, n4w);

    const int PROJ_SMEM = (128 * PADW + 64 * PADW) * 2 * 2;   // 55296 B (>= 128*67*4)
    cudaFuncSetAttribute(proj_mma, cudaFuncAttributeMaxDynamicSharedMemorySize, PROJ_SMEM);
    proj_mma<<<dim3(16, 32, 3), 256, PROJ_SMEM>>>(bq, bk, bv);

    tile_sum_kernel<<<dim3(NB * NH, NT), 64>>>();
    tile_suffix_kernel<<<dim3(NB * NH), 64>>>();
    row_suffix_kernel<<<dim3(NB * NH, NT), 64>>>();

    const int ATTN_SMEM = 3 * 64 * PADW * 2 + (128 + 128 + 128 + 64) * 4;  // 29440 B
    attn_mma<<<dim3(NT, NH, NB), 256, ATTN_SMEM>>>(pos, (float*)d_out);
}

// round 8
// speedup vs baseline: 3.9701x; 1.5648x over previous
#include <cuda_runtime.h>
#include <cuda_bf16.h>
#include <math.h>
#include <stdint.h>

#define NB 2
#define NS 2048
#define NE 1024
#define NH 16
#define ND 64
#define NT 32            // NS / 64 key tiles
#define NEGV (-1e9f)
#define NEGM (-1e30f)
#define QSCALE 0.125f    // 1/sqrt(64)
#define PADW 72          // bf16 elements per smem row
#define KVBUF (64 * PADW)

// Scratch (allocation-free rule: __device__ globals)
__device__ float g_v[NB*NH*NS*ND];              // fp32 projected V (exact path)
__device__ float g_sufx[NB*NH*NS*ND];           // per-row exclusive suffix: sum_{k>s} v[k][d]
__device__ float g_vt[NB*NH*ND];                // total sum_k v[k][d]
__device__ float g_tsum[NB*NH*NT*ND];           // per-tile V sums
__device__ float g_tsuf[NB*NH*NT*ND];           // exclusive tile-level suffix
__device__ __nv_bfloat16 g_qb[NB*NH*NS*ND];     // bf16 Q (pre-scaled by 1/8)
__device__ __nv_bfloat16 g_kb[NB*NH*NS*ND];     // bf16 K
__device__ __nv_bfloat16 g_vtb[NB*NH*NS*ND];    // bf16 V transposed per 64-tile: [bh][t][d][64]
// bf16 inputs: x: 0=query 1=key 2=value_hi 3=value_lo ; w: 0=Wq 1=Wk 2=Wv_hi 3=Wv_lo
__device__ __nv_bfloat16 g_xb[4u*4096*1024];
__device__ __nv_bfloat16 g_wb[4u*1024*1024];

// ---------------------------------------------------------------------------
__device__ __forceinline__ void mma16816(float* c, const uint32_t* a, const uint32_t* b) {
    asm volatile("mma.sync.aligned.m16n8k16.row.col.f32.bf16.bf16.f32 "
        "{%0,%1,%2,%3}, {%4,%5,%6,%7}, {%8,%9}, {%0,%1,%2,%3};"
        : "+f"(c[0]), "+f"(c[1]), "+f"(c[2]), "+f"(c[3])
        : "r"(a[0]), "r"(a[1]), "r"(a[2]), "r"(a[3]), "r"(b[0]), "r"(b[1]));
}
__device__ __forceinline__ uint32_t pack_bf16x2(float a, float b) {
    __nv_bfloat162 t = __floats2bfloat162_rn(a, b);
    return *(uint32_t*)&t;
}
__device__ __forceinline__ uint32_t s2u(const void* p) {
    uint32_t a;
    asm("{ .reg .u64 t; cvta.to.shared.u64 t, %1; cvt.u32.u64 %0, t; }" : "=r"(a) : "l"(p));
    return a;
}
__device__ __forceinline__ void cpa16(uint32_t d, const void* s) {
    asm volatile("cp.async.cg.shared.global [%0], [%1], 16;" :: "r"(d), "l"(s));
}
__device__ __forceinline__ void cpa4(uint32_t d, const void* s) {
    asm volatile("cp.async.ca.shared.global [%0], [%1], 4;" :: "r"(d), "l"(s));
}
#define CP_COMMIT() asm volatile("cp.async.commit_group;" ::: "memory")
#define CP_WAIT1()  asm volatile("cp.async.wait_group 1;" ::: "memory")
#define CP_WAIT0()  asm volatile("cp.async.wait_group 0;" ::: "memory")

// ---------------------------------------------------------------------------
// Kernel 0: fp32 -> bf16 (hi), optionally also residual (lo) into next slice.
// ---------------------------------------------------------------------------
__global__ void f2bf_kernel(const float4* __restrict__ src, int which, int split, int n4)
{
    int i = blockIdx.x * blockDim.x + threadIdx.x;
    if (i >= n4) return;
    __nv_bfloat16* hi = (which < 4)
        ? g_xb + (size_t)which * 4096 * 1024
        : g_wb + (size_t)(which - 4) * 1024 * 1024;
    size_t loOff = (which < 4) ? (size_t)4096 * 1024 : (size_t)1024 * 1024;

    float4 v = src[i];
    __nv_bfloat16 h0 = __float2bfloat16(v.x), h1 = __float2bfloat16(v.y);
    __nv_bfloat16 h2 = __float2bfloat16(v.z), h3 = __float2bfloat16(v.w);
    __nv_bfloat162* dh = (__nv_bfloat162*)hi;
    dh[2*i]   = __nv_bfloat162(h0, h1);
    dh[2*i+1] = __nv_bfloat162(h2, h3);
    if (split) {
        __nv_bfloat162* dl = (__nv_bfloat162*)(hi + loOff);
        dl[2*i]   = __nv_bfloat162(__float2bfloat16(v.x - __bfloat162float(h0)),
                                   __float2bfloat16(v.y - __bfloat162float(h1)));
        dl[2*i+1] = __nv_bfloat162(__float2bfloat16(v.z - __bfloat162float(h2)),
                                   __float2bfloat16(v.w - __bfloat162float(h3)));
    }
}

// ---------------------------------------------------------------------------
// Kernel 1: projections via mma.sync bf16.  2 heads per block (N=128).
// z = 0: Q -> g_qb bf16 (scaled), 1: K -> g_kb, 2: V (3-mma split) -> g_v fp32 + g_vtb bf16^T
// 8 warps = 4(m) x 2(n); warp tile 32(m) x 64(n); K-chunk 64.
// ---------------------------------------------------------------------------
__global__ __launch_bounds__(256) void proj_mma(
    const float* __restrict__ bq, const float* __restrict__ bk, const float* __restrict__ bv)
{
    extern __shared__ __align__(16) char smraw[];
    __nv_bfloat16* Xh = (__nv_bfloat16*)smraw;       // [128][PADW]
    __nv_bfloat16* Wh = Xh + 128 * PADW;             // [128][PADW] (2 heads)
    __nv_bfloat16* Xl = Wh + 128 * PADW;             // (V only)
    __nv_bfloat16* Wl = Xl + 128 * PADW;             // (V only)

    const int z = blockIdx.z;
    const int split = (z == 2);
    const __nv_bfloat16* Xg  = g_xb + (size_t)z * 4096 * 1024;
    const __nv_bfloat16* Wg  = g_wb + (size_t)z * 1024 * 1024;
    const __nv_bfloat16* XgL = Xg + (size_t)4096 * 1024;
    const __nv_bfloat16* WgL = Wg + (size_t)1024 * 1024;
    const float* bias = (z == 0) ? bq : (z == 1) ? bk : bv;

    const int hp = blockIdx.x;                  // head pair 0..7
    const int m0 = blockIdx.y * 128;
    const int tid = threadIdx.x;
    const int wid = tid >> 5, lane = tid & 31;
    const int warpM = wid >> 1, warpN = wid & 1;
    const int gp = lane >> 2, tig = lane & 3;

    float acc[2][8][4] = {};

    for (int c = 0; c < 16; c++) {
        const int k0 = c * 64;
        __syncthreads();
        #pragma unroll
        for (int j = 0; j < 4; j++) {
            int u = tid + j * 256;
            int r = u >> 3, cg = (u & 7) * 8;
            *(uint4*)&Xh[r * PADW + cg] = *(const uint4*)(Xg + (size_t)(m0 + r) * NE + k0 + cg);
            *(uint4*)&Wh[r * PADW + cg] = *(const uint4*)(Wg + (size_t)(hp * 128 + r) * NE + k0 + cg);
            if (split) {
                *(uint4*)&Xl[r * PADW + cg] = *(const uint4*)(XgL + (size_t)(m0 + r) * NE + k0 + cg);
                *(uint4*)&Wl[r * PADW + cg] = *(const uint4*)(WgL + (size_t)(hp * 128 + r) * NE + k0 + cg);
            }
        }
        __syncthreads();

        #pragma unroll
        for (int ks = 0; ks < 4; ks++) {
            const int kc = ks * 16 + tig * 2;
            uint32_t a[2][4], al[2][4];
            #pragma unroll
            for (int mi = 0; mi < 2; mi++) {
                const int r = warpM * 32 + mi * 16 + gp;
                a[mi][0] = *(const uint32_t*)&Xh[(r    ) * PADW + kc];
                a[mi][1] = *(const uint32_t*)&Xh[(r + 8) * PADW + kc];
                a[mi][2] = *(const uint32_t*)&Xh[(r    ) * PADW + kc + 8];
                a[mi][3] = *(const uint32_t*)&Xh[(r + 8) * PADW + kc + 8];
                if (split) {
                    al[mi][0] = *(const uint32_t*)&Xl[(r    ) * PADW + kc];
                    al[mi][1] = *(const uint32_t*)&Xl[(r + 8) * PADW + kc];
                    al[mi][2] = *(const uint32_t*)&Xl[(r    ) * PADW + kc + 8];
                    al[mi][3] = *(const uint32_t*)&Xl[(r + 8) * PADW + kc + 8];
                }
            }
            #pragma unroll
            for (int ni = 0; ni < 8; ni++) {
                const int n = warpN * 64 + ni * 8 + gp;
                uint32_t b[2], bl[2];
                b[0] = *(const uint32_t*)&Wh[n * PADW + kc];
                b[1] = *(const uint32_t*)&Wh[n * PADW + kc + 8];
                if (split) {
                    bl[0] = *(const uint32_t*)&Wl[n * PADW + kc];
                    bl[1] = *(const uint32_t*)&Wl[n * PADW + kc + 8];
                }
                #pragma unroll
                for (int mi = 0; mi < 2; mi++) {
                    mma16816(acc[mi][ni], a[mi], b);
                    if (split) {
                        mma16816(acc[mi][ni], a[mi], bl);
                        mma16816(acc[mi][ni], al[mi], b);
                    }
                }
            }
        }
    }

    const int b  = m0 >> 11;
    const int s0 = m0 & (NS - 1);
    __syncthreads();

    if (z < 2) {
        const float sc = (z == 0) ? QSCALE : 1.0f;
        __nv_bfloat16* dst = (z == 0) ? g_qb : g_kb;
        const int head = hp * 2 + warpN;
        const size_t bh = (size_t)(b * NH + head);
        #pragma unroll
        for (int mi = 0; mi < 2; mi++)
            #pragma unroll
            for (int ni = 0; ni < 8; ni++) {
                const int r = warpM * 32 + mi * 16 + gp;
                const int d = ni * 8 + tig * 2;
                const float bx = bias[head * 64 + d], by = bias[head * 64 + d + 1];
                #pragma unroll
                for (int half = 0; half < 2; half++) {
                    const int s = s0 + r + half * 8;
                    float v0 = (acc[mi][ni][2*half+0] + bx) * sc;
                    float v1 = (acc[mi][ni][2*half+1] + by) * sc;
                    *(uint32_t*)&dst[(bh * NS + s) * ND + d] = pack_bf16x2(v0, v1);
                }
            }
    } else {
        float* Vst = (float*)smraw;    // [128][131] staging
        #pragma unroll
        for (int mi = 0; mi < 2; mi++)
            #pragma unroll
            for (int ni = 0; ni < 8; ni++) {
                const int r = warpM * 32 + mi * 16 + gp;
                const int cn = warpN * 64 + ni * 8 + tig * 2;
                const float bx = bias[hp * 128 + cn], by = bias[hp * 128 + cn + 1];
                #pragma unroll
                for (int half = 0; half < 2; half++) {
                    const int rr = r + half * 8;
                    Vst[rr * 131 + cn    ] = acc[mi][ni][2*half+0] + bx;
                    Vst[rr * 131 + cn + 1] = acc[mi][ni][2*half+1] + by;
                }
            }
        __syncthreads();
        // coalesced fp32 V (2 heads)
        #pragma unroll
        for (int i = 0; i < 16; i++) {
            int u = tid + i * 256;
            int r = u >> 5, c4 = (u & 31) * 4;
            int head = hp * 2 + (c4 >> 6), d = c4 & 63;
            float4 w = make_float4(Vst[r*131+c4], Vst[r*131+c4+1], Vst[r*131+c4+2], Vst[r*131+c4+3]);
            *(float4*)&g_v[((size_t)(b * NH + head) * NS + s0 + r) * ND + d] = w;
        }
        // coalesced transposed bf16 V
        const int t0 = s0 >> 6;
        #pragma unroll
        for (int i = 0; i < 32; i++) {
            int u = tid + i * 256;
            int j = (u & 31) * 2, cc = (u >> 5) & 127, tl = u >> 12;
            int head = hp * 2 + (cc >> 6), d = cc & 63;
            uint32_t p = pack_bf16x2(Vst[(tl*64 + j)*131 + cc], Vst[(tl*64 + j + 1)*131 + cc]);
            *(uint32_t*)&g_vtb[(((size_t)(b * NH + head) * NT + t0 + tl) * ND + d) * 64 + j] = p;
        }
    }
}

// ---------------------------------------------------------------------------
// Kernels 2a/2b/2c: parallel per-row exclusive suffix sums of V.
// ---------------------------------------------------------------------------
__global__ void tile_sum_kernel()
{
    const int bh = blockIdx.x, t = blockIdx.y, d = threadIdx.x;
    const float* v = g_v + ((size_t)bh * NS + t * 64) * ND + d;
    float a = 0.f;
    #pragma unroll 8
    for (int j = 0; j < 64; j++) a += v[(size_t)j * ND];
    g_tsum[((size_t)bh * NT + t) * ND + d] = a;
}
__global__ void tile_suffix_kernel()
{
    const int bh = blockIdx.x, d = threadIdx.x;
    float acc = 0.f;
    for (int t = NT - 1; t >= 0; t--) {
        float tv = g_tsum[((size_t)bh * NT + t) * ND + d];
        g_tsuf[((size_t)bh * NT + t) * ND + d] = acc;
        acc += tv;
    }
    g_vt[bh * ND + d] = acc;
}
__global__ void row_suffix_kernel()
{
    const int bh = blockIdx.x, t = blockIdx.y, d = threadIdx.x;
    float acc = g_tsuf[((size_t)bh * NT + t) * ND + d];
    const float* v = g_v + ((size_t)bh * NS + t * 64) * ND + d;
    float* sx = g_sufx + ((size_t)bh * NS + t * 64) * ND + d;
    for (int j = 63; j >= 0; j--) {
        sx[(size_t)j * ND] = acc;
        acc += v[(size_t)j * ND];
    }
}

// ---------------------------------------------------------------------------
// Kernel 3: register-resident flash-style attention, 3-stage cp.async pipeline.
// ---------------------------------------------------------------------------
__global__ __launch_bounds__(256, 2) void attn_mma(
    const float* __restrict__ pos_bias, float* __restrict__ out)
{
    extern __shared__ __align__(16) char smr[];
    __nv_bfloat16* Qb  = (__nv_bfloat16*)smr;        // [64][72]
    __nv_bfloat16* KV0 = Qb + 64 * PADW;             // 3 slots x (K,V), each 64*PADW
    float* posw  = (float*)(KV0 + 6 * KVBUF);        // [3][128]
    float* pm    = posw + 384;                       // [64][2]
    float* pl    = pm + 128;                         // [64][2]
    float* lse_s = pl + 128;                         // [64]
    float* Obuf  = (float*)smr;                      // overlay [64][66]

    const int tq = NT - 1 - blockIdx.x;              // heavy blocks first
    const int h  = blockIdx.y;
    const int b  = blockIdx.z;
    const int bh = b * NH + h;
    const int q0 = tq * 64;
    const int tid = threadIdx.x;
    const int wid = tid >> 5, lane = tid & 31;
    const int warpM = wid >> 1, warpN = wid & 1;
    const int gp = lane >> 2, tig = lane & 3;
    const int rbase = warpM * 16 + gp;

    // ---- prefetch helper (tile t -> slot s) ----
    auto prefetch = [&](int t, int s) {
        const int k0 = t * 64;
        __nv_bfloat16* Ks = KV0 + s * 2 * KVBUF;
        __nv_bfloat16* Vs = Ks + KVBUF;
        #pragma unroll
        for (int j = 0; j < 2; j++) {
            int u = tid + j * 256;
            int r = u >> 3, cg = (u & 7) * 8;
            cpa16(s2u(&Ks[r * PADW + cg]), g_kb + ((size_t)bh * NS + k0 + r) * ND + cg);
            cpa16(s2u(&Vs[r * PADW + cg]), g_vtb + (((size_t)bh * NT + t) * ND + r) * 64 + cg);
        }
        if (tid < 128) {
            int idx = q0 - k0 - 63 + tid + NS - 1;
            if (idx <= 2 * NS - 2)
                cpa4(s2u(&posw[s * 128 + tid]), &pos_bias[(size_t)h * (2 * NS - 1) + idx]);
            else
                posw[s * 128 + tid] = 0.f;
        }
    };

    prefetch(0, 0); CP_COMMIT();
    if (tq >= 1) prefetch(1, 1);
    CP_COMMIT();

    // Q tile -> smem -> fragments (resident all tiles)
    #pragma unroll
    for (int j = 0; j < 2; j++) {
        int u = tid + j * 256;
        int r = u >> 3, cg = (u & 7) * 8;
        *(uint4*)&Qb[r * PADW + cg] = *(const uint4*)(g_qb + ((size_t)bh * NS + q0 + r) * ND + cg);
    }
    __syncthreads();
    uint32_t aq[4][4];
    #pragma unroll
    for (int ks = 0; ks < 4; ks++) {
        const int kc = ks * 16 + tig * 2;
        aq[ks][0] = *(const uint32_t*)&Qb[(rbase    ) * PADW + kc];
        aq[ks][1] = *(const uint32_t*)&Qb[(rbase + 8) * PADW + kc];
        aq[ks][2] = *(const uint32_t*)&Qb[(rbase    ) * PADW + kc + 8];
        aq[ks][3] = *(const uint32_t*)&Qb[(rbase + 8) * PADW + kc + 8];
    }

    float oacc[8][4] = {};
    float m0r = NEGM, l0r = 0.f, m1r = NEGM, l1r = 0.f;

    for (int t = 0; t <= tq; t++) {
        const bool diag = (t == tq);
        const int s = t % 3;
        CP_WAIT1();                      // tile t's group complete (t+1 may be in flight)
        __syncthreads();
        if (t + 2 <= tq) prefetch(t + 2, (t + 2) % 3);
        CP_COMMIT();                     // always commit (keeps group counts aligned)

        const __nv_bfloat16* Ks = KV0 + s * 2 * KVBUF;
        const __nv_bfloat16* Vs = Ks + KVBUF;
        const float* pw = posw + s * 128;

        // ---- S = Q.K^T over this warp's k-half ----
        float cS[4][4] = {};
        #pragma unroll
        for (int ks = 0; ks < 4; ks++) {
            const int kc = ks * 16 + tig * 2;
            uint32_t bb[4][2];
            #pragma unroll
            for (int ni = 0; ni < 4; ni++) {
                const int n = warpN * 32 + ni * 8 + gp;
                bb[ni][0] = *(const uint32_t*)&Ks[n * PADW + kc];
                bb[ni][1] = *(const uint32_t*)&Ks[n * PADW + kc + 8];
            }
            #pragma unroll
            for (int ni = 0; ni < 4; ni++) mma16816(cS[ni], aq[ks], bb[ni]);
        }

        // ---- bias + mask in registers; pack SV A-frags; lse values ----
        float e0[8], e1[8];
        uint32_t sf[2][4];
        #pragma unroll
        for (int ni = 0; ni < 4; ni++) {
            const int kcol = warpN * 32 + ni * 8 + tig * 2;
            float v00 = cS[ni][0] + pw[rbase     - kcol + 63];
            float v01 = cS[ni][1] + pw[rbase     - kcol + 62];
            float v10 = cS[ni][2] + pw[rbase + 8 - kcol + 63];
            float v11 = cS[ni][3] + pw[rbase + 8 - kcol + 62];
            float p00 = v00, p01 = v01, p10 = v10, p11 = v11;
            if (diag) {
                if (kcol     > rbase)     { v00 = NEGM; p00 = 0.f; }
                if (kcol + 1 > rbase)     { v01 = NEGM; p01 = 0.f; }
                if (kcol     > rbase + 8) { v10 = NEGM; p10 = 0.f; }
                if (kcol + 1 > rbase + 8) { v11 = NEGM; p11 = 0.f; }
            }
            e0[ni*2] = v00; e0[ni*2+1] = v01;
            e1[ni*2] = v10; e1[ni*2+1] = v11;
            const int ks2 = ni >> 1;
            if ((ni & 1) == 0) {
                sf[ks2][0] = pack_bf16x2(p00, p01);
                sf[ks2][1] = pack_bf16x2(p10, p11);
            } else {
                sf[ks2][2] = pack_bf16x2(p00, p01);
                sf[ks2][3] = pack_bf16x2(p10, p11);
            }
        }
        // ---- online lse (register-only) ----
        {
            float vm = e0[0];
            #pragma unroll
            for (int j = 1; j < 8; j++) vm = fmaxf(vm, e0[j]);
            float mn = fmaxf(m0r, vm);
            float sum = 0.f;
            #pragma unroll
            for (int j = 0; j < 8; j++) sum += __expf(e0[j] - mn);
            l0r = l0r * __expf(m0r - mn) + sum; m0r = mn;
        }
        {
            float vm = e1[0];
            #pragma unroll
            for (int j = 1; j < 8; j++) vm = fmaxf(vm, e1[j]);
            float mn = fmaxf(m1r, vm);
            float sum = 0.f;
            #pragma unroll
            for (int j = 0; j < 8; j++) sum += __expf(e1[j] - mn);
            l1r = l1r * __expf(m1r - mn) + sum; m1r = mn;
        }

        // ---- O += S.V over this warp's k-half (full 64 d) ----
        #pragma unroll
        for (int ks2 = 0; ks2 < 2; ks2++) {
            const int kc = warpN * 32 + ks2 * 16 + tig * 2;
            #pragma unroll
            for (int ni = 0; ni < 8; ni++) {
                const int n = ni * 8 + gp;
                uint32_t bb[2];
                bb[0] = *(const uint32_t*)&Vs[n * PADW + kc];
                bb[1] = *(const uint32_t*)&Vs[n * PADW + kc + 8];
                mma16816(oacc[ni], sf[ks2], bb);
            }
        }
    }

    CP_WAIT0();
    __syncthreads();
    // reduce (m,l) across tig lanes
    #pragma unroll
    for (int d = 1; d < 4; d <<= 1) {
        float mo = __shfl_xor_sync(0xffffffffu, m0r, d);
        float lo = __shfl_xor_sync(0xffffffffu, l0r, d);
        float mn = fmaxf(m0r, mo);
        l0r = l0r * __expf(m0r - mn) + lo * __expf(mo - mn); m0r = mn;
        mo = __shfl_xor_sync(0xffffffffu, m1r, d);
        lo = __shfl_xor_sync(0xffffffffu, l1r, d);
        mn = fmaxf(m1r, mo);
        l1r = l1r * __expf(m1r - mn) + lo * __expf(mo - mn); m1r = mn;
    }
    if (tig == 0) {
        pm[rbase * 2 + warpN] = m0r;       pl[rbase * 2 + warpN] = l0r;
        pm[(rbase + 8) * 2 + warpN] = m1r; pl[(rbase + 8) * 2 + warpN] = l1r;
    }
    __syncthreads();
    if (tid < 64) {
        float ma = pm[tid*2], mb_ = pm[tid*2+1], la = pl[tid*2], lb = pl[tid*2+1];
        float mn = fmaxf(ma, mb_);
        lse_s[tid] = mn + logf(la * __expf(ma - mn) + lb * __expf(mb_ - mn));
    }
    __syncthreads();
    // cross-warpN O combine
    if (warpN == 1) {
        #pragma unroll
        for (int ni = 0; ni < 8; ni++) {
            const int d = ni * 8 + tig * 2;
            Obuf[rbase * 66 + d]           = oacc[ni][0];
            Obuf[rbase * 66 + d + 1]       = oacc[ni][1];
            Obuf[(rbase + 8) * 66 + d]     = oacc[ni][2];
            Obuf[(rbase + 8) * 66 + d + 1] = oacc[ni][3];
        }
    }
    __syncthreads();
    if (warpN == 0) {
        const float lse0 = lse_s[rbase], lse1 = lse_s[rbase + 8];
        const int q0r = q0 + rbase;
        #pragma unroll
        for (int ni = 0; ni < 8; ni++) {
            const int d = ni * 8 + tig * 2;
            float2 vt2 = *(const float2*)&g_vt[bh * ND + d];
            float2 sx0 = *(const float2*)&g_sufx[((size_t)bh * NS + q0r    ) * ND + d];
            float2 sx1 = *(const float2*)&g_sufx[((size_t)bh * NS + q0r + 8) * ND + d];
            float2 o0, o1;
            o0.x = oacc[ni][0] + Obuf[rbase * 66 + d]     + NEGV * sx0.x - lse0 * vt2.x;
            o0.y = oacc[ni][1] + Obuf[rbase * 66 + d + 1] + NEGV * sx0.y - lse0 * vt2.y;
            o1.x = oacc[ni][2] + Obuf[(rbase+8) * 66 + d]     + NEGV * sx1.x - lse1 * vt2.x;
            o1.y = oacc[ni][3] + Obuf[(rbase+8) * 66 + d + 1] + NEGV * sx1.y - lse1 * vt2.y;
            *(float2*)&out[(((size_t)b * NS + q0r    ) * NH + h) * ND + d] = o0;
            *(float2*)&out[(((size_t)b * NS + q0r + 8) * NH + h) * ND + d] = o1;
        }
    }
}

// ---------------------------------------------------------------------------
extern "C" void kernel_launch(void* const* d_in, const int* in_sizes, int n_in,
                              void* d_out, int out_size)
{
    (void)in_sizes; (void)n_in; (void)out_size;
    const float* query = (const float*)d_in[0];
    const float* key_  = (const float*)d_in[1];
    const float* value = (const float*)d_in[2];
    const float* Wq    = (const float*)d_in[3];
    const float* bq    = (const float*)d_in[4];
    const float* Wk    = (const float*)d_in[5];
    const float* bk    = (const float*)d_in[6];
    const float* Wv    = (const float*)d_in[7];
    const float* bv    = (const float*)d_in[8];
    const float* pos   = (const float*)d_in[9];

    const int n4x = 4096 * 1024 / 4, n4w = 1024 * 1024 / 4;
    f2bf_kernel<<<n4x / 256, 256>>>((const float4*)query, 0, 0, n4x);
    f2bf_kernel<<<n4x / 256, 256>>>((const float4*)key_,  1, 0, n4x);
    f2bf_kernel<<<n4x / 256, 256>>>((const float4*)value, 2, 1, n4x);
    f2bf_kernel<<<n4w / 256, 256>>>((const float4*)Wq,    4, 0, n4w);
    f2bf_kernel<<<n4w / 256, 256>>>((const float4*)Wk,    5, 0, n4w);
    f2bf_kernel<<<n4w / 256, 256>>>((const float4*)Wv,    6, 1, n4w);

    const int PROJ_SMEM = 4 * 128 * PADW * 2;   // 73728 B
    cudaFuncSetAttribute(proj_mma, cudaFuncAttributeMaxDynamicSharedMemorySize, PROJ_SMEM);
    proj_mma<<<dim3(8, 32, 3), 256, PROJ_SMEM>>>(bq, bk, bv);

    tile_sum_kernel<<<dim3(NB * NH, NT), 64>>>();
    tile_suffix_kernel<<<dim3(NB * NH), 64>>>();
    row_suffix_kernel<<<dim3(NB * NH, NT), 64>>>();

    // Qb + 3*(K,V) + posw[3][128] + pm/pl/lse
    const int ATTN_SMEM = 64*PADW*2 + 6*KVBUF*2 + (384 + 128 + 128 + 64) * 4;  // 67328 B
    cudaFuncSetAttribute(attn_mma, cudaFuncAttributeMaxDynamicSharedMemorySize, ATTN_SMEM);
    attn_mma<<<dim3(NT, NH, NB), 256, ATTN_SMEM>>>(pos, (float*)d_out);
}